// round 5
// baseline (speedup 1.0000x reference)
#include <cuda_runtime.h>
#include <cuda_fp16.h>
#include <math.h>
#include <stdint.h>

#define NMAX 100000
#define EMAX 1600000
#define DD 64
#define SCAN_B 256        // scan grid blocks (256*512 = 131072 >= NMAX)

// ---------------- device scratch (no allocations allowed) ----------------
__device__ int    g_counts[NMAX];
__device__ int    g_fill[NMAX];
__device__ int    g_rowptr[NMAX + 1];
__device__ int    g_esrc[EMAX];
__device__ int    g_blocksums[SCAN_B];
__device__ int    g_blockoff[SCAN_B];
__device__ __half g_yh[(size_t)NMAX * DD];   // fp16 activations (gather operand)
__device__ float  g_yf[(size_t)NMAX * DD];   // fp32 activations (self rows)
__device__ float  g_agg[(size_t)NMAX * DD];  // fp32 aggregation output
__device__ float  g_M1[DD * DD];
__device__ float  g_M2[DD * DD];
__device__ float  g_v[DD];
__device__ float  g_bias;
__device__ int    g_is64;

// ------------- zero counts + detect edge dtype (merged) ------------------
__global__ void prep_kernel(const void* __restrict__ edges, int N) {
    int i = blockIdx.x * blockDim.x + threadIdx.x;
    if (i < N) g_counts[i] = 0;
    if (blockIdx.x == 0) {
        __shared__ int nz;
        if (threadIdx.x == 0) nz = 0;
        __syncthreads();
        const int* w = (const int*)edges;
        int local = 0;
        for (int k = threadIdx.x; k < 2048; k += blockDim.x)
            if (w[2 * k + 1] != 0) local = 1;
        if (local) atomicOr(&nz, 1);
        __syncthreads();
        if (threadIdx.x == 0) g_is64 = (nz == 0) ? 1 : 0;
    }
}

__global__ void hist_kernel(const void* __restrict__ edges, int E) {
    int e = blockIdx.x * blockDim.x + threadIdx.x;
    if (e >= E) return;
    int dst;
    if (g_is64) dst = (int)((const long long*)edges)[E + e];
    else        dst = ((const int*)edges)[E + e];
    atomicAdd(&g_counts[dst], 1);
}

// ---------------- 3-phase parallel exclusive scan -------------------------
__global__ void scan_p1(int N) {
    __shared__ int sm[256];
    int b = blockIdx.x, t = threadIdx.x;
    int base = b * 512 + t * 2;
    int s = 0;
    if (base < N)     s += g_counts[base];
    if (base + 1 < N) s += g_counts[base + 1];
    sm[t] = s;
    __syncthreads();
    for (int off = 128; off; off >>= 1) {
        if (t < off) sm[t] += sm[t + off];
        __syncthreads();
    }
    if (t == 0) g_blocksums[b] = sm[0];
}

__global__ void scan_p2(int N) {
    __shared__ int sm[SCAN_B];
    int t = threadIdx.x;
    int orig = g_blocksums[t];
    sm[t] = orig;
    __syncthreads();
    for (int off = 1; off < SCAN_B; off <<= 1) {
        int v = (t >= off) ? sm[t - off] : 0;
        __syncthreads();
        sm[t] += v;
        __syncthreads();
    }
    g_blockoff[t] = sm[t] - orig;
    if (t == SCAN_B - 1) g_rowptr[N] = sm[t];
}

__global__ void scan_p3(int N) {
    __shared__ int sm[256];
    int b = blockIdx.x, t = threadIdx.x;
    int base = b * 512 + t * 2;
    int c0 = (base < N) ? g_counts[base] : 0;
    int c1 = (base + 1 < N) ? g_counts[base + 1] : 0;
    int s = c0 + c1;
    sm[t] = s;
    __syncthreads();
    for (int off = 1; off < 256; off <<= 1) {
        int v = (t >= off) ? sm[t - off] : 0;
        __syncthreads();
        sm[t] += v;
        __syncthreads();
    }
    int pre = sm[t] - s + g_blockoff[b];
    if (base < N)     { g_rowptr[base] = pre;          g_fill[base] = pre; }
    if (base + 1 < N) { g_rowptr[base + 1] = pre + c0; g_fill[base + 1] = pre + c0; }
}

__global__ void scatter_kernel(const void* __restrict__ edges, int E) {
    int e = blockIdx.x * blockDim.x + threadIdx.x;
    if (e >= E) return;
    int src, dst;
    if (g_is64) {
        const long long* p = (const long long*)edges;
        src = (int)p[e]; dst = (int)p[E + e];
    } else {
        const int* p = (const int*)edges;
        src = p[e]; dst = p[E + e];
    }
    int pos = atomicAdd(&g_fill[dst], 1);
    g_esrc[pos] = src;
}

// fold weights: M1 = Wp1*Wt0, M2 = Wp2*Wt1, v = Wout*Wt2, bias
__global__ void matprep_kernel(const float* __restrict__ Wp,
                               const float* __restrict__ Wt,
                               const float* __restrict__ Wout,
                               const float* __restrict__ bout) {
    int t = blockIdx.x * blockDim.x + threadIdx.x;
    if (t >= DD * DD) return;
    int i = t >> 6, k = t & 63;
    float s1 = 0.f, s2 = 0.f;
#pragma unroll
    for (int m = 0; m < DD; m++) {
        s1 += Wp[1 * DD * DD + i * DD + m] * Wt[0 * DD * DD + m * DD + k];
        s2 += Wp[2 * DD * DD + i * DD + m] * Wt[1 * DD * DD + m * DD + k];
    }
    g_M1[t] = s1;
    g_M2[t] = s2;
    if (i == 0) {
        float sv = 0.f;
#pragma unroll
        for (int m = 0; m < DD; m++)
            sv += Wout[m] * Wt[2 * DD * DD + m * DD + k];
        g_v[k] = sv;
    }
    if (t == 0) g_bias = bout[0];
}

// ---------------- GEMM: dual-write fp32 + fp16 ---------------------------
__global__ void gemm_kernel(const float* __restrict__ x,
                            const float* __restrict__ M,
                            float* __restrict__ outf,
                            __half* __restrict__ outh, int N) {
    __shared__ float sx[DD][DD + 1];
    __shared__ float sM[DD][DD + 1];
    int t = threadIdx.x;
    int base = blockIdx.x * DD;

#pragma unroll
    for (int i = 0; i < 4; i++) {
        int v = t + 256 * i;
        int r = v >> 4;
        int c4 = (v & 15) * 4;
        float4 mv = *(const float4*)&M[r * DD + c4];
        sM[r][c4] = mv.x; sM[r][c4 + 1] = mv.y; sM[r][c4 + 2] = mv.z; sM[r][c4 + 3] = mv.w;
        float4 xv = make_float4(0.f, 0.f, 0.f, 0.f);
        if (base + r < N)
            xv = *(const float4*)&x[(size_t)(base + r) * DD + c4];
        sx[r][c4] = xv.x; sx[r][c4 + 1] = xv.y; sx[r][c4 + 2] = xv.z; sx[r][c4 + 3] = xv.w;
    }
    __syncthreads();

    int tc = (t & 15) * 4;
    int tr = (t >> 4) * 4;
    float acc[4][4];
#pragma unroll
    for (int i = 0; i < 4; i++)
#pragma unroll
        for (int j = 0; j < 4; j++) acc[i][j] = 0.f;

#pragma unroll 16
    for (int k = 0; k < DD; k++) {
        float a0 = sx[tr][k], a1 = sx[tr + 1][k], a2 = sx[tr + 2][k], a3 = sx[tr + 3][k];
        float b0 = sM[tc][k], b1 = sM[tc + 1][k], b2 = sM[tc + 2][k], b3 = sM[tc + 3][k];
        acc[0][0] += a0 * b0; acc[0][1] += a0 * b1; acc[0][2] += a0 * b2; acc[0][3] += a0 * b3;
        acc[1][0] += a1 * b0; acc[1][1] += a1 * b1; acc[1][2] += a1 * b2; acc[1][3] += a1 * b3;
        acc[2][0] += a2 * b0; acc[2][1] += a2 * b1; acc[2][2] += a2 * b2; acc[2][3] += a2 * b3;
        acc[3][0] += a3 * b0; acc[3][1] += a3 * b1; acc[3][2] += a3 * b2; acc[3][3] += a3 * b3;
    }

#pragma unroll
    for (int i = 0; i < 4; i++) {
        int row = base + tr + i;
        if (row < N) {
            *(float4*)&outf[(size_t)row * DD + tc] =
                make_float4(acc[i][0], acc[i][1], acc[i][2], acc[i][3]);
            __half2 h0 = __floats2half2_rn(acc[i][0], acc[i][1]);
            __half2 h1 = __floats2half2_rn(acc[i][2], acc[i][3]);
            uint2 pack;
            pack.x = *(const unsigned*)&h0;
            pack.y = *(const unsigned*)&h1;
            *(uint2*)&outh[(size_t)row * DD + tc] = pack;
        }
    }
}

// ---------------- aggregation core (fp16 gather, MLP=4) -------------------
// Warp per node; half-warp per edge; lane owns 4 columns via one 8B load.
// 8 edges per unrolled iteration -> 4 independent LDG.64 in flight per lane.
// Tail edges processed redundantly by both halves (max idempotent).
__device__ __forceinline__ void agg_core_h(const __half* __restrict__ yh,
                                           int beg, int end, int lane,
                                           __half2& m01, __half2& m23) {
    const __half2 ninf = __float2half2_rn(-INFINITY);
    m01 = ninf; m23 = ninf;
    int half_id = lane >> 4;
    int q = lane & 15;
    for (int b = beg; b < end; b += 32) {
        int cnt = end - b; if (cnt > 32) cnt = 32;
        int idx = (b + lane < end) ? g_esrc[b + lane] : 0;
        int p = 0;
        for (; p + 8 <= cnt; p += 8) {       // 4 edges per half-warp in flight
            int jA = __shfl_sync(0xffffffffu, idx, p + half_id);
            int jB = __shfl_sync(0xffffffffu, idx, p + 2 + half_id);
            int jC = __shfl_sync(0xffffffffu, idx, p + 4 + half_id);
            int jD = __shfl_sync(0xffffffffu, idx, p + 6 + half_id);
            uint2 a = *(const uint2*)&yh[(size_t)jA * DD + q * 4];
            uint2 c = *(const uint2*)&yh[(size_t)jB * DD + q * 4];
            uint2 d = *(const uint2*)&yh[(size_t)jC * DD + q * 4];
            uint2 e = *(const uint2*)&yh[(size_t)jD * DD + q * 4];
            m01 = __hmax2(m01, __hmax2(__hmax2(*(__half2*)&a.x, *(__half2*)&c.x),
                                       __hmax2(*(__half2*)&d.x, *(__half2*)&e.x)));
            m23 = __hmax2(m23, __hmax2(__hmax2(*(__half2*)&a.y, *(__half2*)&c.y),
                                       __hmax2(*(__half2*)&d.y, *(__half2*)&e.y)));
        }
        if (p + 4 <= cnt) {                  // 2 edges per half-warp
            int jA = __shfl_sync(0xffffffffu, idx, p + half_id);
            int jB = __shfl_sync(0xffffffffu, idx, p + 2 + half_id);
            uint2 a = *(const uint2*)&yh[(size_t)jA * DD + q * 4];
            uint2 c = *(const uint2*)&yh[(size_t)jB * DD + q * 4];
            m01 = __hmax2(m01, __hmax2(*(__half2*)&a.x, *(__half2*)&c.x));
            m23 = __hmax2(m23, __hmax2(*(__half2*)&a.y, *(__half2*)&c.y));
            p += 4;
        }
        for (; p < cnt; p++) {               // tail: both halves duplicate
            int j = __shfl_sync(0xffffffffu, idx, p);
            uint2 a = *(const uint2*)&yh[(size_t)j * DD + q * 4];
            m01 = __hmax2(m01, *(__half2*)&a.x);
            m23 = __hmax2(m23, *(__half2*)&a.y);
        }
    }
    unsigned u01 = *(unsigned*)&m01, u23 = *(unsigned*)&m23;
    unsigned o01 = __shfl_xor_sync(0xffffffffu, u01, 16);
    unsigned o23 = __shfl_xor_sync(0xffffffffu, u23, 16);
    m01 = __hmax2(m01, *(__half2*)&o01);
    m23 = __hmax2(m23, *(__half2*)&o23);
}

// agg[i] = max_{src} yh[src] - yf[i]  (fp32 self; 0 for isolated nodes)
__global__ void agg_kernel(const __half* __restrict__ yh,
                           const float* __restrict__ yf,
                           float* __restrict__ out, int N) {
    int wid = (blockIdx.x * blockDim.x + threadIdx.x) >> 5;
    int lane = threadIdx.x & 31;
    if (wid >= N) return;
    int beg = g_rowptr[wid];
    int end = g_rowptr[wid + 1];
    __half2 m01, m23;
    agg_core_h(yh, beg, end, lane, m01, m23);
    if (lane < 16) {
        int q = lane;
        float4 o;
        if (beg == end) {
            o = make_float4(0.f, 0.f, 0.f, 0.f);
        } else {
            float4 s = *(const float4*)&yf[(size_t)wid * DD + q * 4];
            float2 f01 = __half22float2(m01);
            float2 f23 = __half22float2(m23);
            o.x = f01.x - s.x; o.y = f01.y - s.y;
            o.z = f23.x - s.z; o.w = f23.y - s.w;
        }
        *(float4*)&out[(size_t)wid * DD + q * 4] = o;
    }
}

// last layer: agg + dot with folded head vector + sigmoid, fused.
__global__ void agg_final_kernel(const __half* __restrict__ yh,
                                 const float* __restrict__ yf,
                                 float* __restrict__ out, int N) {
    int wid = (blockIdx.x * blockDim.x + threadIdx.x) >> 5;
    int lane = threadIdx.x & 31;
    if (wid >= N) return;
    int beg = g_rowptr[wid];
    int end = g_rowptr[wid + 1];
    __half2 m01, m23;
    agg_core_h(yh, beg, end, lane, m01, m23);
    int q = lane & 15;
    float p = 0.f;
    if (beg != end) {
        float4 s = *(const float4*)&yf[(size_t)wid * DD + q * 4];
        float2 f01 = __half22float2(m01);
        float2 f23 = __half22float2(m23);
        float4 vv = *(const float4*)&g_v[q * 4];
        p = (f01.x - s.x) * vv.x + (f01.y - s.y) * vv.y
          + (f23.x - s.z) * vv.z + (f23.y - s.w) * vv.w;
    }
#pragma unroll
    for (int off = 8; off; off >>= 1)
        p += __shfl_xor_sync(0xffffffffu, p, off);
    if (lane == 0)
        out[wid] = 1.f / (1.f + expf(-(p + g_bias)));
}

extern "C" void kernel_launch(void* const* d_in, const int* in_sizes, int n_in,
                              void* d_out, int out_size) {
    const float* x     = (const float*)d_in[0];
    const void*  edges = d_in[1];
    const float* Wp    = (const float*)d_in[2];
    const float* Wt    = (const float*)d_in[3];
    const float* Wout  = (const float*)d_in[4];
    const float* bout  = (const float*)d_in[5];
    float* out = (float*)d_out;

    int N = in_sizes[0] / DD;
    int E = in_sizes[1] / 2;

    __half* yhp;
    float *yfp, *aggp, *m1p, *m2p;
    cudaGetSymbolAddress((void**)&yhp, g_yh);
    cudaGetSymbolAddress((void**)&yfp, g_yf);
    cudaGetSymbolAddress((void**)&aggp, g_agg);
    cudaGetSymbolAddress((void**)&m1p, g_M1);
    cudaGetSymbolAddress((void**)&m2p, g_M2);

    const int TB = 256;
    int ebl = (E + TB - 1) / TB;
    int nbl = (N + TB - 1) / TB;
    int wbl = ((N * 32) + TB - 1) / TB;   // warp-per-node grids
    int gbl = (N + DD - 1) / DD;          // 64-row GEMM tiles

    prep_kernel<<<nbl, TB>>>(edges, N);
    hist_kernel<<<ebl, TB>>>(edges, E);
    scan_p1<<<SCAN_B, 256>>>(N);
    scan_p2<<<1, SCAN_B>>>(N);
    scan_p3<<<SCAN_B, 256>>>(N);
    scatter_kernel<<<ebl, TB>>>(edges, E);
    matprep_kernel<<<16, 256>>>(Wp, Wt, Wout, bout);

    // layer 0
    gemm_kernel<<<gbl, 256>>>(x, Wp, yfp, yhp, N);
    agg_kernel<<<wbl, TB>>>(yhp, yfp, aggp, N);
    // layer 1
    gemm_kernel<<<gbl, 256>>>(aggp, m1p, yfp, yhp, N);
    agg_kernel<<<wbl, TB>>>(yhp, yfp, aggp, N);
    // layer 2 + head
    gemm_kernel<<<gbl, 256>>>(aggp, m2p, yfp, yhp, N);
    agg_final_kernel<<<wbl, TB>>>(yhp, yfp, out, N);
}

// round 6
// speedup vs baseline: 1.0565x; 1.0565x over previous
#include <cuda_runtime.h>
#include <cuda_fp16.h>
#include <math.h>
#include <stdint.h>

#define NMAX 100000
#define EMAX 1600000
#define DD 64
#define SCB 200          // scan blocks; 200*512 = 102400 >= NMAX; all co-resident

// ---------------- device scratch (no allocations allowed) ----------------
__device__ int    g_counts[NMAX];        // zeroed by scan_fused after use
__device__ int    g_fill[NMAX];
__device__ int    g_rowptr[NMAX + 1];
__device__ int    g_esrc[EMAX];          // BYTE offsets: src * 128
__device__ int    g_bsum[SCB];
__device__ unsigned long long g_barctr;  // monotonic, never reset (replay-safe)
__device__ __half g_yh[(size_t)NMAX * DD];
__device__ float  g_agg[(size_t)NMAX * DD];
__device__ float  g_M1[DD * DD];
__device__ float  g_M2[DD * DD];
__device__ float  g_v[DD];
__device__ float  g_bias;
__device__ int    g_is64;

// ---------------- dtype detection for edges (int64 vs int32) -------------
__global__ void detect_kernel(const void* __restrict__ edges) {
    __shared__ int nz;
    if (threadIdx.x == 0) nz = 0;
    __syncthreads();
    const int* w = (const int*)edges;
    int local = 0;
    for (int i = threadIdx.x; i < 2048; i += blockDim.x)
        if (w[2 * i + 1] != 0) local = 1;
    if (local) atomicOr(&nz, 1);
    __syncthreads();
    if (threadIdx.x == 0) g_is64 = (nz == 0) ? 1 : 0;
}

__global__ void hist_kernel(const void* __restrict__ edges, int E) {
    int e = blockIdx.x * blockDim.x + threadIdx.x;
    if (e >= E) return;
    int dst;
    if (g_is64) dst = (int)((const long long*)edges)[E + e];
    else        dst = ((const int*)edges)[E + e];
    atomicAdd(&g_counts[dst], 1);
}

// ---------------- fused: matprep + single-kernel scan ---------------------
// 200 blocks x 256 threads, all co-resident -> monotonic global barrier is
// deadlock-free and needs no reset across graph replays.
__device__ __forceinline__ void grid_barrier_200() {
    __syncthreads();
    if (threadIdx.x == 0) {
        unsigned long long my = atomicAdd(&g_barctr, 1ULL) + 1ULL;
        unsigned long long target = ((my + SCB - 1) / SCB) * (unsigned long long)SCB;
        while (atomicAdd(&g_barctr, 0ULL) < target) { }
        __threadfence();
    }
    __syncthreads();
}

__global__ void scan_fused(const float* __restrict__ Wp,
                           const float* __restrict__ Wt,
                           const float* __restrict__ Wout,
                           const float* __restrict__ bout, int N) {
    int b = blockIdx.x, t = threadIdx.x;

    // ---- matprep on blocks 0..15 (4096 lanes) ----
    if (b < 16) {
        int id = b * 256 + t;
        int i = id >> 6, k = id & 63;
        float s1 = 0.f, s2 = 0.f;
#pragma unroll
        for (int m = 0; m < DD; m++) {
            s1 += Wp[1 * DD * DD + i * DD + m] * Wt[0 * DD * DD + m * DD + k];
            s2 += Wp[2 * DD * DD + i * DD + m] * Wt[1 * DD * DD + m * DD + k];
        }
        g_M1[id] = s1;
        g_M2[id] = s2;
        if (i == 0) {
            float sv = 0.f;
#pragma unroll
            for (int m = 0; m < DD; m++)
                sv += Wout[m] * Wt[2 * DD * DD + m * DD + k];
            g_v[k] = sv;
        }
        if (id == 0) g_bias = bout[0];
    }

    // ---- phase 1: block sum over its 512-element chunk ----
    __shared__ int sm[256];
    int base = b * 512 + t * 2;
    int c0 = (base < N) ? g_counts[base] : 0;
    int c1 = (base + 1 < N) ? g_counts[base + 1] : 0;
    int s = c0 + c1;
    sm[t] = s;
    __syncthreads();
    for (int off = 128; off; off >>= 1) {
        if (t < off) sm[t] += sm[t + off];
        __syncthreads();
    }
    if (t == 0) { g_bsum[b] = sm[0]; __threadfence(); }

    grid_barrier_200();

    // ---- phase 2a: block offset = exclusive prefix of g_bsum ----
    __shared__ int sb[256];
    sb[t] = (t < SCB) ? g_bsum[t] : 0;
    __syncthreads();
    for (int off = 1; off < 256; off <<= 1) {
        int v = (t >= off) ? sb[t - off] : 0;
        __syncthreads();
        sb[t] += v;
        __syncthreads();
    }
    int blockoff = (b == 0) ? 0 : sb[b - 1];
    if (b == SCB - 1 && t == 0) g_rowptr[N] = sb[SCB - 1];

    // ---- phase 2b: local exclusive scan + write + zero counts ----
    sm[t] = s;
    __syncthreads();
    for (int off = 1; off < 256; off <<= 1) {
        int v = (t >= off) ? sm[t - off] : 0;
        __syncthreads();
        sm[t] += v;
        __syncthreads();
    }
    int pre = sm[t] - s + blockoff;
    if (base < N)     { g_rowptr[base] = pre;          g_fill[base] = pre;          g_counts[base] = 0; }
    if (base + 1 < N) { g_rowptr[base + 1] = pre + c0; g_fill[base + 1] = pre + c0; g_counts[base + 1] = 0; }
}

__global__ void scatter_kernel(const void* __restrict__ edges, int E) {
    int e = blockIdx.x * blockDim.x + threadIdx.x;
    if (e >= E) return;
    int src, dst;
    if (g_is64) {
        const long long* p = (const long long*)edges;
        src = (int)p[e]; dst = (int)p[E + e];
    } else {
        const int* p = (const int*)edges;
        src = p[e]; dst = p[E + e];
    }
    int pos = atomicAdd(&g_fill[dst], 1);
    g_esrc[pos] = src << 7;              // byte offset into fp16 rows (64*2B)
}

// ---------------- GEMM: yh[64-row tile] = half( in @ M^T ) ---------------
__global__ void gemm_kernel(const float* __restrict__ x,
                            const float* __restrict__ M,
                            __half* __restrict__ out, int N) {
    __shared__ float sx[DD][DD + 1];
    __shared__ float sM[DD][DD + 1];
    int t = threadIdx.x;
    int base = blockIdx.x * DD;

#pragma unroll
    for (int i = 0; i < 4; i++) {
        int v = t + 256 * i;
        int r = v >> 4;
        int c4 = (v & 15) * 4;
        float4 mv = *(const float4*)&M[r * DD + c4];
        sM[r][c4] = mv.x; sM[r][c4 + 1] = mv.y; sM[r][c4 + 2] = mv.z; sM[r][c4 + 3] = mv.w;
        float4 xv = make_float4(0.f, 0.f, 0.f, 0.f);
        if (base + r < N)
            xv = *(const float4*)&x[(size_t)(base + r) * DD + c4];
        sx[r][c4] = xv.x; sx[r][c4 + 1] = xv.y; sx[r][c4 + 2] = xv.z; sx[r][c4 + 3] = xv.w;
    }
    __syncthreads();

    int tc = (t & 15) * 4;
    int tr = (t >> 4) * 4;
    float acc[4][4];
#pragma unroll
    for (int i = 0; i < 4; i++)
#pragma unroll
        for (int j = 0; j < 4; j++) acc[i][j] = 0.f;

#pragma unroll 16
    for (int k = 0; k < DD; k++) {
        float a0 = sx[tr][k], a1 = sx[tr + 1][k], a2 = sx[tr + 2][k], a3 = sx[tr + 3][k];
        float b0 = sM[tc][k], b1 = sM[tc + 1][k], b2 = sM[tc + 2][k], b3 = sM[tc + 3][k];
        acc[0][0] += a0 * b0; acc[0][1] += a0 * b1; acc[0][2] += a0 * b2; acc[0][3] += a0 * b3;
        acc[1][0] += a1 * b0; acc[1][1] += a1 * b1; acc[1][2] += a1 * b2; acc[1][3] += a1 * b3;
        acc[2][0] += a2 * b0; acc[2][1] += a2 * b1; acc[2][2] += a2 * b2; acc[2][3] += a2 * b3;
        acc[3][0] += a3 * b0; acc[3][1] += a3 * b1; acc[3][2] += a3 * b2; acc[3][3] += a3 * b3;
    }

#pragma unroll
    for (int i = 0; i < 4; i++) {
        int row = base + tr + i;
        if (row < N) {
            __half2 h0 = __floats2half2_rn(acc[i][0], acc[i][1]);
            __half2 h1 = __floats2half2_rn(acc[i][2], acc[i][3]);
            uint2 pack;
            pack.x = *(const unsigned*)&h0;
            pack.y = *(const unsigned*)&h1;
            *(uint2*)&out[(size_t)row * DD + tc] = pack;
        }
    }
}

// ---------------- aggregation core (fp16 gather, uniform-ldg indices) -----
// Warp per node; half-warp per edge; lane owns 4 columns (one 8B load).
// Edge byte-offsets read via uniform __ldg (L1 line reused 32x) - no SHFL.
__device__ __forceinline__ void agg_core_h(const __half* __restrict__ yh,
                                           int beg, int end, int lane,
                                           __half2& m01, __half2& m23) {
    const __half2 ninf = __float2half2_rn(-INFINITY);
    m01 = ninf; m23 = ninf;
    const char* Y = (const char*)yh;
    int half_id = lane >> 4;
    int qb = (lane & 15) * 8;
    int p = beg;
    for (; p + 8 <= end; p += 8) {         // 4 edges per half-warp
        int o0 = __ldg(&g_esrc[p     + half_id]);
        int o1 = __ldg(&g_esrc[p + 2 + half_id]);
        int o2 = __ldg(&g_esrc[p + 4 + half_id]);
        int o3 = __ldg(&g_esrc[p + 6 + half_id]);
        uint2 a = *(const uint2*)(Y + o0 + qb);
        uint2 c = *(const uint2*)(Y + o1 + qb);
        uint2 d = *(const uint2*)(Y + o2 + qb);
        uint2 e = *(const uint2*)(Y + o3 + qb);
        m01 = __hmax2(m01, __hmax2(__hmax2(*(__half2*)&a.x, *(__half2*)&c.x),
                                   __hmax2(*(__half2*)&d.x, *(__half2*)&e.x)));
        m23 = __hmax2(m23, __hmax2(__hmax2(*(__half2*)&a.y, *(__half2*)&c.y),
                                   __hmax2(*(__half2*)&d.y, *(__half2*)&e.y)));
    }
    if (p + 4 <= end) {                    // 2 edges per half-warp
        int o0 = __ldg(&g_esrc[p     + half_id]);
        int o1 = __ldg(&g_esrc[p + 2 + half_id]);
        uint2 a = *(const uint2*)(Y + o0 + qb);
        uint2 c = *(const uint2*)(Y + o1 + qb);
        m01 = __hmax2(m01, __hmax2(*(__half2*)&a.x, *(__half2*)&c.x));
        m23 = __hmax2(m23, __hmax2(*(__half2*)&a.y, *(__half2*)&c.y));
        p += 4;
    }
    for (; p < end; p++) {                 // tail: both halves duplicate
        int o = __ldg(&g_esrc[p]);
        uint2 a = *(const uint2*)(Y + o + qb);
        m01 = __hmax2(m01, *(__half2*)&a.x);
        m23 = __hmax2(m23, *(__half2*)&a.y);
    }
    unsigned u01 = *(unsigned*)&m01, u23 = *(unsigned*)&m23;
    unsigned o01 = __shfl_xor_sync(0xffffffffu, u01, 16);
    unsigned o23 = __shfl_xor_sync(0xffffffffu, u23, 16);
    m01 = __hmax2(m01, *(__half2*)&o01);
    m23 = __hmax2(m23, *(__half2*)&o23);
}

// agg[i] = max_{src} yh[src] - yh[i]  (0 for isolated nodes)
__global__ void agg_kernel(const __half* __restrict__ yh,
                           float* __restrict__ out, int N) {
    int wid = (blockIdx.x * blockDim.x + threadIdx.x) >> 5;
    int lane = threadIdx.x & 31;
    if (wid >= N) return;
    int beg = g_rowptr[wid];
    int end = g_rowptr[wid + 1];
    __half2 m01, m23;
    agg_core_h(yh, beg, end, lane, m01, m23);
    if (lane < 16) {
        int q = lane;
        float4 o;
        if (beg == end) {
            o = make_float4(0.f, 0.f, 0.f, 0.f);
        } else {
            uint2 sp = *(const uint2*)&yh[(size_t)wid * DD + q * 4];
            float2 f01 = __half22float2(m01);
            float2 f23 = __half22float2(m23);
            float2 s01 = __half22float2(*(__half2*)&sp.x);
            float2 s23 = __half22float2(*(__half2*)&sp.y);
            o.x = f01.x - s01.x; o.y = f01.y - s01.y;
            o.z = f23.x - s23.x; o.w = f23.y - s23.y;
        }
        *(float4*)&out[(size_t)wid * DD + q * 4] = o;
    }
}

// last layer: agg + dot with folded head vector + sigmoid, fused.
__global__ void agg_final_kernel(const __half* __restrict__ yh,
                                 float* __restrict__ out, int N) {
    int wid = (blockIdx.x * blockDim.x + threadIdx.x) >> 5;
    int lane = threadIdx.x & 31;
    if (wid >= N) return;
    int beg = g_rowptr[wid];
    int end = g_rowptr[wid + 1];
    __half2 m01, m23;
    agg_core_h(yh, beg, end, lane, m01, m23);
    int q = lane & 15;
    float p = 0.f;
    if (beg != end) {
        uint2 sp = *(const uint2*)&yh[(size_t)wid * DD + q * 4];
        float2 f01 = __half22float2(m01);
        float2 f23 = __half22float2(m23);
        float2 s01 = __half22float2(*(__half2*)&sp.x);
        float2 s23 = __half22float2(*(__half2*)&sp.y);
        float4 vv = *(const float4*)&g_v[q * 4];
        p = (f01.x - s01.x) * vv.x + (f01.y - s01.y) * vv.y
          + (f23.x - s23.x) * vv.z + (f23.y - s23.y) * vv.w;
    }
#pragma unroll
    for (int off = 8; off; off >>= 1)
        p += __shfl_xor_sync(0xffffffffu, p, off);
    if (lane == 0)
        out[wid] = 1.f / (1.f + expf(-(p + g_bias)));
}

extern "C" void kernel_launch(void* const* d_in, const int* in_sizes, int n_in,
                              void* d_out, int out_size) {
    const float* x     = (const float*)d_in[0];
    const void*  edges = d_in[1];
    const float* Wp    = (const float*)d_in[2];
    const float* Wt    = (const float*)d_in[3];
    const float* Wout  = (const float*)d_in[4];
    const float* bout  = (const float*)d_in[5];
    float* out = (float*)d_out;

    int N = in_sizes[0] / DD;
    int E = in_sizes[1] / 2;

    __half* yhp;
    float *aggp, *m1p, *m2p;
    cudaGetSymbolAddress((void**)&yhp, g_yh);
    cudaGetSymbolAddress((void**)&aggp, g_agg);
    cudaGetSymbolAddress((void**)&m1p, g_M1);
    cudaGetSymbolAddress((void**)&m2p, g_M2);

    const int TB = 256;
    int ebl = (E + TB - 1) / TB;
    int wbl = ((N * 32) + TB - 1) / TB;   // warp-per-node grids
    int gbl = (N + DD - 1) / DD;          // 64-row GEMM tiles

    detect_kernel<<<1, 256>>>(edges);
    hist_kernel<<<ebl, TB>>>(edges, E);
    scan_fused<<<SCB, 256>>>(Wp, Wt, Wout, bout, N);
    scatter_kernel<<<ebl, TB>>>(edges, E);

    // layer 0
    gemm_kernel<<<gbl, 256>>>(x, Wp, yhp, N);
    agg_kernel<<<wbl, TB>>>(yhp, aggp, N);
    // layer 1
    gemm_kernel<<<gbl, 256>>>(aggp, m1p, yhp, N);
    agg_kernel<<<wbl, TB>>>(yhp, aggp, N);
    // layer 2 + head
    gemm_kernel<<<gbl, 256>>>(aggp, m2p, yhp, N);
    agg_final_kernel<<<wbl, TB>>>(yhp, out, N);
}